// round 1
// baseline (speedup 1.0000x reference)
#include <cuda_runtime.h>
#include <cstdio>

#define H 64
#define NNODES 100000
#define NEDGES 1600000

// ---------------- device scratch (static: no dynamic allocation allowed) ----
__device__ float        g_h[(size_t)NNODES * H];
__device__ float        g_A[(size_t)NNODES * H];
__device__ unsigned int g_aggr[(size_t)NNODES * H];
__device__ int          g_cnt[NNODES];
__device__ int          g_cursor[NNODES];
__device__ int          g_perm[NEDGES];

// order-preserving float<->uint encoding for atomic min
__device__ __forceinline__ unsigned fenc(float f) {
    unsigned u = __float_as_uint(f);
    return (u & 0x80000000u) ? ~u : (u | 0x80000000u);
}
__device__ __forceinline__ float fdec(unsigned u) {
    return (u & 0x80000000u) ? __uint_as_float(u & 0x7FFFFFFFu)
                             : __uint_as_float(~u);
}

// ---------------- trivial elementwise kernels ------------------------------
__global__ void embed_kernel(const float* __restrict__ x,
                             const float* __restrict__ w,
                             const float* __restrict__ b,
                             float* __restrict__ h, int n) {
    int i = blockIdx.x * blockDim.x + threadIdx.x;
    if (i < n * H) {
        int node = i >> 6, j = i & 63;
        h[i] = fmaf(x[node], w[j], b[j]);
    }
}

__global__ void count_kernel(const int* __restrict__ dst, int* cnt, int e) {
    int i = blockIdx.x * blockDim.x + threadIdx.x;
    if (i < e) atomicAdd(&cnt[dst[i]], 1);
}

__global__ void scan_kernel(const int* __restrict__ cnt,
                            int* __restrict__ cursor, int n) {
    __shared__ int s[1024];
    int tid = threadIdx.x;
    int chunk = (n + 1023) >> 10;
    int lo = tid * chunk;
    int hi = min(lo + chunk, n);
    int sum = 0;
    for (int i = lo; i < hi; i++) sum += cnt[i];
    s[tid] = sum;
    __syncthreads();
    for (int off = 1; off < 1024; off <<= 1) {
        int v = (tid >= off) ? s[tid - off] : 0;
        __syncthreads();
        s[tid] += v;
        __syncthreads();
    }
    int run = s[tid] - sum;  // exclusive prefix for this chunk
    for (int i = lo; i < hi; i++) { cursor[i] = run; run += cnt[i]; }
}

__global__ void scatter_kernel(const int* __restrict__ dst, int* cursor,
                               int* perm, int e) {
    int i = blockIdx.x * blockDim.x + threadIdx.x;
    if (i < e) {
        int p = atomicAdd(&cursor[dst[i]], 1);
        perm[p] = i;
    }
}

// aggr (encoded uint min, no b2) -> float aggr with b2 added; empty -> 0
__global__ void finalize_kernel(unsigned* __restrict__ a,
                                const float* __restrict__ b2, int n) {
    int i = blockIdx.x * blockDim.x + threadIdx.x;
    if (i < n * H) {
        unsigned u = a[i];
        float f = (u >= 0xFF800000u) ? 0.0f : (fdec(u) + b2[i & 63]);
        ((float*)a)[i] = f;
    }
}

__global__ void fc_kernel(const float* __restrict__ h,
                          const float* __restrict__ fcw,
                          const float* __restrict__ fcb,
                          float* __restrict__ out, int n) {
    int i = blockIdx.x * blockDim.x + threadIdx.x;
    if (i >= n) return;
    const float4* h4 = (const float4*)(h + (size_t)i * H);
    const float4* w4 = (const float4*)fcw;
    float s = 0.f;
#pragma unroll
    for (int q = 0; q < 16; q++) {
        float4 a = h4[q], w = w4[q];
        s += a.x * w.x + a.y * w.y + a.z * w.z + a.w * w.w;
    }
    out[i] = s + fcb[0];
}

// ---------------- generic node-side tiled GEMM -----------------------------
// C[N,64] = act( [X1 | X2] @ W + bias ), K = 64 or 128, 128 rows per block,
// 128 threads, 8x8 register tile per thread.
template <int K, bool RELU>
__global__ void __launch_bounds__(128)
node_gemm(const float* __restrict__ X1, const float* __restrict__ X2,
          const float* __restrict__ W, const float* __restrict__ bias,
          float* __restrict__ C, int Nn) {
    extern __shared__ float sm[];
    float* Ws = sm;                 // K*64
    float* Xs = sm + K * 64;        // K*128 (transposed: Xs[k][row])
    int tid = threadIdx.x;
    int n0 = blockIdx.x * 128;

    // load W (K*64 floats)
    {
        const float4* W4 = (const float4*)W;
        float4* Ws4 = (float4*)Ws;
#pragma unroll
        for (int i = 0; i < K / 8; i++) Ws4[tid + i * 128] = W4[tid + i * 128];
    }
    // load X rows (thread = row), store transposed (conflict-free: addr = c + tid)
    {
        int n = min(n0 + tid, Nn - 1);
        const float4* X14 = (const float4*)(X1 + (size_t)n * H);
#pragma unroll
        for (int q = 0; q < 16; q++) {
            float4 v = X14[q];
            Xs[(4 * q + 0) * 128 + tid] = v.x;
            Xs[(4 * q + 1) * 128 + tid] = v.y;
            Xs[(4 * q + 2) * 128 + tid] = v.z;
            Xs[(4 * q + 3) * 128 + tid] = v.w;
        }
        if (K == 128) {
            const float4* X24 = (const float4*)(X2 + (size_t)n * H);
#pragma unroll
            for (int q = 0; q < 16; q++) {
                float4 v = X24[q];
                Xs[(64 + 4 * q + 0) * 128 + tid] = v.x;
                Xs[(64 + 4 * q + 1) * 128 + tid] = v.y;
                Xs[(64 + 4 * q + 2) * 128 + tid] = v.z;
                Xs[(64 + 4 * q + 3) * 128 + tid] = v.w;
            }
        }
    }
    __syncthreads();

    int ty = tid >> 3, tx = tid & 7;
    float acc[8][8];
#pragma unroll
    for (int r = 0; r < 8; r++)
#pragma unroll
        for (int c = 0; c < 8; c++) acc[r][c] = 0.f;

    const float4* Xs4 = (const float4*)Xs;
    const float4* Ws4 = (const float4*)Ws;
#pragma unroll 8
    for (int k = 0; k < K; k++) {
        float4 a0 = Xs4[k * 32 + ty * 2];
        float4 a1 = Xs4[k * 32 + ty * 2 + 1];
        float4 b0 = Ws4[k * 16 + tx * 2];
        float4 b1 = Ws4[k * 16 + tx * 2 + 1];
        float av[8] = {a0.x, a0.y, a0.z, a0.w, a1.x, a1.y, a1.z, a1.w};
        float bv[8] = {b0.x, b0.y, b0.z, b0.w, b1.x, b1.y, b1.z, b1.w};
#pragma unroll
        for (int r = 0; r < 8; r++)
#pragma unroll
            for (int c = 0; c < 8; c++)
                acc[r][c] = fmaf(av[r], bv[c], acc[r][c]);
    }

    float bb[8];
#pragma unroll
    for (int c = 0; c < 8; c++) bb[c] = bias[tx * 8 + c];

#pragma unroll
    for (int r = 0; r < 8; r++) {
        int n = n0 + ty * 8 + r;
        if (n < Nn) {
            float4 o0, o1;
            o0.x = acc[r][0] + bb[0]; o0.y = acc[r][1] + bb[1];
            o0.z = acc[r][2] + bb[2]; o0.w = acc[r][3] + bb[3];
            o1.x = acc[r][4] + bb[4]; o1.y = acc[r][5] + bb[5];
            o1.z = acc[r][6] + bb[6]; o1.w = acc[r][7] + bb[7];
            if (RELU) {
                o0.x = fmaxf(o0.x, 0.f); o0.y = fmaxf(o0.y, 0.f);
                o0.z = fmaxf(o0.z, 0.f); o0.w = fmaxf(o0.w, 0.f);
                o1.x = fmaxf(o1.x, 0.f); o1.y = fmaxf(o1.y, 0.f);
                o1.z = fmaxf(o1.z, 0.f); o1.w = fmaxf(o1.w, 0.f);
            }
            float4* C4 = (float4*)(C + (size_t)n * H);
            C4[tx * 2] = o0;
            C4[tx * 2 + 1] = o1;
        }
    }
}

// ---------------- fused edge kernel ----------------------------------------
// For 128 sorted-by-dst edges: t = relu(A[src] + e*we); m = t @ W2;
// thread-local segmented min over 8 consecutive edges, then atomicMin (REDG).
__global__ void __launch_bounds__(128)
edge_kernel(const float* __restrict__ A, const float* __restrict__ W2,
            const float* __restrict__ we_g, const int* __restrict__ src,
            const int* __restrict__ dst, const float* __restrict__ ea,
            const int* __restrict__ perm, unsigned int* __restrict__ aggr,
            int E) {
    extern __shared__ float sm[];
    float* W2s = sm;                       // 4096
    float* wes = sm + 4096;                // 64
    float* Ts  = sm + 4160;                // 64*128 (transposed: Ts[k][edge])
    int*   srcL = (int*)(sm + 12352);      // 128
    float* evL  = sm + 12480;              // 128
    int*   dstL = (int*)(sm + 12608);      // 128

    int tid = threadIdx.x;
    int e0 = blockIdx.x * 128;

    // load W2 + we
    {
        const float4* W24 = (const float4*)W2;
        float4* W2s4 = (float4*)W2s;
#pragma unroll
        for (int i = 0; i < 8; i++) W2s4[tid + i * 128] = W24[tid + i * 128];
        if (tid < 64) wes[tid] = we_g[tid];
    }
    // edge metadata
    {
        int slot = e0 + tid;
        int eidx = perm[min(slot, E - 1)];
        srcL[tid] = src[eidx];
        evL[tid] = ea[eidx];
        dstL[tid] = (slot < E) ? dst[eidx] : -1;
    }
    __syncthreads();

    // stage t for this thread's edge (gathered A row is L2-resident)
    {
        int s = srcL[tid];
        float ev = evL[tid];
        const float4* A4 = (const float4*)(A + (size_t)s * H);
#pragma unroll
        for (int q = 0; q < 16; q++) {
            float4 a = A4[q];
            Ts[(4 * q + 0) * 128 + tid] = fmaxf(fmaf(ev, wes[4 * q + 0], a.x), 0.f);
            Ts[(4 * q + 1) * 128 + tid] = fmaxf(fmaf(ev, wes[4 * q + 1], a.y), 0.f);
            Ts[(4 * q + 2) * 128 + tid] = fmaxf(fmaf(ev, wes[4 * q + 2], a.z), 0.f);
            Ts[(4 * q + 3) * 128 + tid] = fmaxf(fmaf(ev, wes[4 * q + 3], a.w), 0.f);
        }
    }
    __syncthreads();

    int ty = tid >> 3, tx = tid & 7;
    float acc[8][8];
#pragma unroll
    for (int r = 0; r < 8; r++)
#pragma unroll
        for (int c = 0; c < 8; c++) acc[r][c] = 0.f;

    const float4* Ts4 = (const float4*)Ts;
    const float4* W2s4 = (const float4*)W2s;
#pragma unroll 8
    for (int k = 0; k < 64; k++) {
        float4 a0 = Ts4[k * 32 + ty * 2];
        float4 a1 = Ts4[k * 32 + ty * 2 + 1];
        float4 b0 = W2s4[k * 16 + tx * 2];
        float4 b1 = W2s4[k * 16 + tx * 2 + 1];
        float av[8] = {a0.x, a0.y, a0.z, a0.w, a1.x, a1.y, a1.z, a1.w};
        float bv[8] = {b0.x, b0.y, b0.z, b0.w, b1.x, b1.y, b1.z, b1.w};
#pragma unroll
        for (int r = 0; r < 8; r++)
#pragma unroll
            for (int c = 0; c < 8; c++)
                acc[r][c] = fmaf(av[r], bv[c], acc[r][c]);
    }

    // thread-local segmented min over 8 consecutive sorted edges, then REDG.
    // b2 is NOT added here: min(m + b2) = min(m) + b2, applied in finalize.
    int cur = dstL[ty * 8];
    float mn[8];
#pragma unroll
    for (int c = 0; c < 8; c++) mn[c] = acc[0][c];
#pragma unroll
    for (int r = 1; r < 8; r++) {
        int d = dstL[ty * 8 + r];
        if (d == cur) {
#pragma unroll
            for (int c = 0; c < 8; c++) mn[c] = fminf(mn[c], acc[r][c]);
        } else {
            if (cur >= 0) {
                unsigned* base = aggr + (size_t)cur * H + tx * 8;
#pragma unroll
                for (int c = 0; c < 8; c++) atomicMin(base + c, fenc(mn[c]));
            }
            cur = d;
#pragma unroll
            for (int c = 0; c < 8; c++) mn[c] = acc[r][c];
        }
    }
    if (cur >= 0) {
        unsigned* base = aggr + (size_t)cur * H + tx * 8;
#pragma unroll
        for (int c = 0; c < 8; c++) atomicMin(base + c, fenc(mn[c]));
    }
}

// ---------------- host launch ----------------------------------------------
extern "C" void kernel_launch(void* const* d_in, const int* in_sizes, int n_in,
                              void* d_out, int out_size) {
    const float* x    = (const float*)d_in[0];
    const int*   ei   = (const int*)d_in[1];
    const float* ea   = (const float*)d_in[2];
    const float* embw = (const float*)d_in[3];
    const float* embb = (const float*)d_in[4];
    const float* mw1  = (const float*)d_in[5];
    const float* mb1  = (const float*)d_in[6];
    const float* mw2  = (const float*)d_in[7];
    const float* mb2  = (const float*)d_in[8];
    const float* uw1  = (const float*)d_in[9];
    const float* ub1  = (const float*)d_in[10];
    const float* uw2  = (const float*)d_in[11];
    const float* ub2  = (const float*)d_in[12];
    const float* fcw  = (const float*)d_in[13];
    const float* fcb  = (const float*)d_in[14];
    float* out = (float*)d_out;

    int N = in_sizes[0];        // NF = 1
    int E = in_sizes[2];        // EF = 1
    int L = in_sizes[6] / H;    // msg_b1 is [L, H]
    const int* src = ei;
    const int* dstp = ei + E;

    float* hbuf; float* Abuf; unsigned* aggr; int* cnt; int* cursor; int* perm;
    cudaGetSymbolAddress((void**)&hbuf, g_h);
    cudaGetSymbolAddress((void**)&Abuf, g_A);
    cudaGetSymbolAddress((void**)&aggr, g_aggr);
    cudaGetSymbolAddress((void**)&cnt, g_cnt);
    cudaGetSymbolAddress((void**)&cursor, g_cursor);
    cudaGetSymbolAddress((void**)&perm, g_perm);

    const size_t smE   = (4096 + 64 + 64 * 128) * 4 + 128 * 4 * 3;  // 50944 B
    const size_t sm64  = (64 * 64 + 64 * 128) * 4;                   // 49152 B
    const size_t sm128 = (128 * 64 + 128 * 128) * 4;                 // 98304 B
    cudaFuncSetAttribute(edge_kernel,
                         cudaFuncAttributeMaxDynamicSharedMemorySize, (int)smE);
    cudaFuncSetAttribute(node_gemm<64, false>,
                         cudaFuncAttributeMaxDynamicSharedMemorySize, (int)sm64);
    cudaFuncSetAttribute(node_gemm<128, true>,
                         cudaFuncAttributeMaxDynamicSharedMemorySize, (int)sm128);

    // embedding
    embed_kernel<<<(N * H + 255) / 256, 256>>>(x, embw, embb, hbuf, N);

    // counting sort of edges by dst (dst fixed across layers -> once per launch)
    cudaMemsetAsync(cnt, 0, (size_t)N * sizeof(int));
    count_kernel<<<(E + 255) / 256, 256>>>(dstp, cnt, E);
    scan_kernel<<<1, 1024>>>(cnt, cursor, N);
    scatter_kernel<<<(E + 255) / 256, 256>>>(dstp, cursor, perm, E);

    int nodeBlocks = (N + 127) / 128;
    int edgeBlocks = (E + 127) / 128;

    for (int l = 0; l < L; l++) {
        const float* w1 = mw1 + (size_t)l * (H + 1) * H;   // [65,64]
        // A = h @ W1[:64] + b1   (per-node hoist of the per-edge msg layer 1)
        node_gemm<64, false><<<nodeBlocks, 128, sm64>>>(
            hbuf, nullptr, w1, mb1 + (size_t)l * H, Abuf, N);
        // aggr identity = encoded +inf (0xFF bytes decode above enc(+inf))
        cudaMemsetAsync(aggr, 0xFF, (size_t)N * H * sizeof(unsigned));
        // fused: t=relu(A[src]+e*we); m=t@W2; segmented atomic min by dst
        edge_kernel<<<edgeBlocks, 128, smE>>>(
            Abuf, mw2 + (size_t)l * H * H, w1 + (size_t)H * H,
            src, dstp, ea, perm, aggr, E);
        // decode + add msg_b2; empty segments -> 0
        finalize_kernel<<<(N * H + 255) / 256, 256>>>(
            aggr, mb2 + (size_t)l * H, N);
        // update MLP: tmp = relu([h|aggr] @ uw1 + ub1); h = tmp @ uw2 + ub2
        node_gemm<128, true><<<nodeBlocks, 128, sm128>>>(
            hbuf, (const float*)aggr, uw1 + (size_t)l * 2 * H * H,
            ub1 + (size_t)l * H, Abuf, N);
        node_gemm<64, false><<<nodeBlocks, 128, sm64>>>(
            Abuf, nullptr, uw2 + (size_t)l * H * H, ub2 + (size_t)l * H,
            hbuf, N);
    }

    fc_kernel<<<(N + 255) / 256, 256>>>(hbuf, fcw, fcb, out, N);
}

// round 2
// speedup vs baseline: 1.0375x; 1.0375x over previous
#include <cuda_runtime.h>
#include <cstdio>

#define H 64
#define NNODES 100000
#define NEDGES 1600000

typedef unsigned long long u64;

// ---------------- device scratch (static: no dynamic allocation allowed) ----
__device__ float        g_h[(size_t)NNODES * H];
__device__ float        g_A[(size_t)NNODES * H];
__device__ unsigned int g_aggr[(size_t)NNODES * H];
__device__ int          g_cnt[NNODES];
__device__ int          g_cursor[NNODES];
__device__ int          g_perm[NEDGES];

// order-preserving float<->uint encoding for atomic min
__device__ __forceinline__ unsigned fenc(float f) {
    unsigned u = __float_as_uint(f);
    return (u & 0x80000000u) ? ~u : (u | 0x80000000u);
}
__device__ __forceinline__ float fdec(unsigned u) {
    return (u & 0x80000000u) ? __uint_as_float(u & 0x7FFFFFFFu)
                             : __uint_as_float(~u);
}

// -------- packed f32x2 helpers (SASS FFMA2 — 2 lane-FMAs per fma-pipe issue)
__device__ __forceinline__ u64 pk_dup(float x) {
    u64 r;
    asm("mov.b64 %0, {%1,%1};" : "=l"(r) : "f"(x));
    return r;
}
__device__ __forceinline__ void fma2(u64& d, u64 a, u64 b) {
    asm("fma.rn.f32x2 %0, %1, %2, %3;" : "=l"(d) : "l"(a), "l"(b), "l"(d));
}
__device__ __forceinline__ void unpk(float& lo, float& hi, u64 v) {
    asm("mov.b64 {%0,%1}, %2;" : "=f"(lo), "=f"(hi) : "l"(v));
}

// ---------------- trivial elementwise kernels ------------------------------
__global__ void embed_kernel(const float* __restrict__ x,
                             const float* __restrict__ w,
                             const float* __restrict__ b,
                             float* __restrict__ h, int n) {
    int i = blockIdx.x * blockDim.x + threadIdx.x;
    if (i < n * H) {
        int node = i >> 6, j = i & 63;
        h[i] = fmaf(x[node], w[j], b[j]);
    }
}

__global__ void count_kernel(const int* __restrict__ dst, int* cnt, int e) {
    int i = blockIdx.x * blockDim.x + threadIdx.x;
    if (i < e) atomicAdd(&cnt[dst[i]], 1);
}

__global__ void scan_kernel(const int* __restrict__ cnt,
                            int* __restrict__ cursor, int n) {
    __shared__ int s[1024];
    int tid = threadIdx.x;
    int chunk = (n + 1023) >> 10;
    int lo = tid * chunk;
    int hi = min(lo + chunk, n);
    int sum = 0;
    for (int i = lo; i < hi; i++) sum += cnt[i];
    s[tid] = sum;
    __syncthreads();
    for (int off = 1; off < 1024; off <<= 1) {
        int v = (tid >= off) ? s[tid - off] : 0;
        __syncthreads();
        s[tid] += v;
        __syncthreads();
    }
    int run = s[tid] - sum;  // exclusive prefix for this chunk
    for (int i = lo; i < hi; i++) { cursor[i] = run; run += cnt[i]; }
}

__global__ void scatter_kernel(const int* __restrict__ dst, int* cursor,
                               int* perm, int e) {
    int i = blockIdx.x * blockDim.x + threadIdx.x;
    if (i < e) {
        int p = atomicAdd(&cursor[dst[i]], 1);
        perm[p] = i;
    }
}

// aggr (encoded uint min, no b2) -> float aggr with b2 added; empty -> 0
__global__ void finalize_kernel(unsigned* __restrict__ a,
                                const float* __restrict__ b2, int n) {
    int i = blockIdx.x * blockDim.x + threadIdx.x;
    if (i < n * H) {
        unsigned u = a[i];
        float f = (u >= 0xFF800000u) ? 0.0f : (fdec(u) + b2[i & 63]);
        ((float*)a)[i] = f;
    }
}

__global__ void fc_kernel(const float* __restrict__ h,
                          const float* __restrict__ fcw,
                          const float* __restrict__ fcb,
                          float* __restrict__ out, int n) {
    int i = blockIdx.x * blockDim.x + threadIdx.x;
    if (i >= n) return;
    const float4* h4 = (const float4*)(h + (size_t)i * H);
    const float4* w4 = (const float4*)fcw;
    float s = 0.f;
#pragma unroll
    for (int q = 0; q < 16; q++) {
        float4 a = h4[q], w = w4[q];
        s += a.x * w.x + a.y * w.y + a.z * w.z + a.w * w.w;
    }
    out[i] = s + fcb[0];
}

// -------- shared packed-f32x2 8x8 microkernel body -------------------------
// acc2[r][cp] accumulates output pair (cols tx*8+2cp, +1) for row ty*8+r.
// Xs: [K][128] transposed activations; Ws: [K][64] weights (cols contiguous).
template <int K>
__device__ __forceinline__ void gemm_body(const float* Xs, const float* Ws,
                                          int ty, int tx, u64 acc2[8][4]) {
    const float4* Xs4 = (const float4*)Xs;
#pragma unroll 4
    for (int k = 0; k < K; k++) {
        float4 a0 = Xs4[k * 32 + ty * 2];
        float4 a1 = Xs4[k * 32 + ty * 2 + 1];
        const ulonglong2* Wp =
            (const ulonglong2*)(Ws + k * 64 + tx * 8);
        ulonglong2 w01 = Wp[0];   // LDS.128: col pairs 0,1
        ulonglong2 w23 = Wp[1];   // LDS.128: col pairs 2,3
        u64 aa[8] = {pk_dup(a0.x), pk_dup(a0.y), pk_dup(a0.z), pk_dup(a0.w),
                     pk_dup(a1.x), pk_dup(a1.y), pk_dup(a1.z), pk_dup(a1.w)};
#pragma unroll
        for (int r = 0; r < 8; r++) {
            fma2(acc2[r][0], aa[r], w01.x);
            fma2(acc2[r][1], aa[r], w01.y);
            fma2(acc2[r][2], aa[r], w23.x);
            fma2(acc2[r][3], aa[r], w23.y);
        }
    }
}

// ---------------- generic node-side tiled GEMM -----------------------------
// C[N,64] = act( [X1 | X2] @ W + bias ), K = 64 or 128, 128 rows per block,
// 128 threads, 8x8 register tile per thread (packed f32x2 accumulators).
template <int K, bool RELU>
__global__ void __launch_bounds__(128)
node_gemm(const float* __restrict__ X1, const float* __restrict__ X2,
          const float* __restrict__ W, const float* __restrict__ bias,
          float* __restrict__ C, int Nn) {
    extern __shared__ float sm[];
    float* Ws = sm;                 // K*64
    float* Xs = sm + K * 64;        // K*128 (transposed: Xs[k][row])
    int tid = threadIdx.x;
    int n0 = blockIdx.x * 128;

    // load W (K*64 floats)
    {
        const float4* W4 = (const float4*)W;
        float4* Ws4 = (float4*)Ws;
#pragma unroll
        for (int i = 0; i < K / 8; i++) Ws4[tid + i * 128] = W4[tid + i * 128];
    }
    // load X rows (thread = row), store transposed (conflict-free: addr = c + tid)
    {
        int n = min(n0 + tid, Nn - 1);
        const float4* X14 = (const float4*)(X1 + (size_t)n * H);
#pragma unroll
        for (int q = 0; q < 16; q++) {
            float4 v = X14[q];
            Xs[(4 * q + 0) * 128 + tid] = v.x;
            Xs[(4 * q + 1) * 128 + tid] = v.y;
            Xs[(4 * q + 2) * 128 + tid] = v.z;
            Xs[(4 * q + 3) * 128 + tid] = v.w;
        }
        if (K == 128) {
            const float4* X24 = (const float4*)(X2 + (size_t)n * H);
#pragma unroll
            for (int q = 0; q < 16; q++) {
                float4 v = X24[q];
                Xs[(64 + 4 * q + 0) * 128 + tid] = v.x;
                Xs[(64 + 4 * q + 1) * 128 + tid] = v.y;
                Xs[(64 + 4 * q + 2) * 128 + tid] = v.z;
                Xs[(64 + 4 * q + 3) * 128 + tid] = v.w;
            }
        }
    }
    __syncthreads();

    int ty = tid >> 3, tx = tid & 7;
    u64 acc2[8][4];
#pragma unroll
    for (int r = 0; r < 8; r++)
#pragma unroll
        for (int c = 0; c < 4; c++) acc2[r][c] = 0ull;

    gemm_body<K>(Xs, Ws, ty, tx, acc2);

    float bb[8];
#pragma unroll
    for (int c = 0; c < 8; c++) bb[c] = bias[tx * 8 + c];

#pragma unroll
    for (int r = 0; r < 8; r++) {
        int n = n0 + ty * 8 + r;
        if (n < Nn) {
            float o[8];
            unpk(o[0], o[1], acc2[r][0]);
            unpk(o[2], o[3], acc2[r][1]);
            unpk(o[4], o[5], acc2[r][2]);
            unpk(o[6], o[7], acc2[r][3]);
            float4 o0, o1;
            o0.x = o[0] + bb[0]; o0.y = o[1] + bb[1];
            o0.z = o[2] + bb[2]; o0.w = o[3] + bb[3];
            o1.x = o[4] + bb[4]; o1.y = o[5] + bb[5];
            o1.z = o[6] + bb[6]; o1.w = o[7] + bb[7];
            if (RELU) {
                o0.x = fmaxf(o0.x, 0.f); o0.y = fmaxf(o0.y, 0.f);
                o0.z = fmaxf(o0.z, 0.f); o0.w = fmaxf(o0.w, 0.f);
                o1.x = fmaxf(o1.x, 0.f); o1.y = fmaxf(o1.y, 0.f);
                o1.z = fmaxf(o1.z, 0.f); o1.w = fmaxf(o1.w, 0.f);
            }
            float4* C4 = (float4*)(C + (size_t)n * H);
            C4[tx * 2] = o0;
            C4[tx * 2 + 1] = o1;
        }
    }
}

// ---------------- fused edge kernel ----------------------------------------
// For 128 sorted-by-dst edges: t = relu(A[src] + e*we); m = t @ W2;
// thread-local segmented min over 8 consecutive edges, then atomicMin (REDG).
__global__ void __launch_bounds__(128)
edge_kernel(const float* __restrict__ A, const float* __restrict__ W2,
            const float* __restrict__ we_g, const int* __restrict__ src,
            const int* __restrict__ dst, const float* __restrict__ ea,
            const int* __restrict__ perm, unsigned int* __restrict__ aggr,
            int E) {
    extern __shared__ float sm[];
    float* W2s = sm;                       // 4096
    float* wes = sm + 4096;                // 64
    float* Ts  = sm + 4160;                // 64*128 (transposed: Ts[k][edge])
    int*   srcL = (int*)(sm + 12352);      // 128
    float* evL  = sm + 12480;              // 128
    int*   dstL = (int*)(sm + 12608);      // 128

    int tid = threadIdx.x;
    int e0 = blockIdx.x * 128;

    // load W2 + we
    {
        const float4* W24 = (const float4*)W2;
        float4* W2s4 = (float4*)W2s;
#pragma unroll
        for (int i = 0; i < 8; i++) W2s4[tid + i * 128] = W24[tid + i * 128];
        if (tid < 64) wes[tid] = we_g[tid];
    }
    // edge metadata
    {
        int slot = e0 + tid;
        int eidx = perm[min(slot, E - 1)];
        srcL[tid] = src[eidx];
        evL[tid] = ea[eidx];
        dstL[tid] = (slot < E) ? dst[eidx] : -1;
    }
    __syncthreads();

    // stage t for this thread's edge (gathered A row is L2-resident)
    {
        int s = srcL[tid];
        float ev = evL[tid];
        const float4* A4 = (const float4*)(A + (size_t)s * H);
#pragma unroll
        for (int q = 0; q < 16; q++) {
            float4 a = A4[q];
            Ts[(4 * q + 0) * 128 + tid] = fmaxf(fmaf(ev, wes[4 * q + 0], a.x), 0.f);
            Ts[(4 * q + 1) * 128 + tid] = fmaxf(fmaf(ev, wes[4 * q + 1], a.y), 0.f);
            Ts[(4 * q + 2) * 128 + tid] = fmaxf(fmaf(ev, wes[4 * q + 2], a.z), 0.f);
            Ts[(4 * q + 3) * 128 + tid] = fmaxf(fmaf(ev, wes[4 * q + 3], a.w), 0.f);
        }
    }
    __syncthreads();

    int ty = tid >> 3, tx = tid & 7;
    u64 acc2[8][4];
#pragma unroll
    for (int r = 0; r < 8; r++)
#pragma unroll
        for (int c = 0; c < 4; c++) acc2[r][c] = 0ull;

    gemm_body<64>(Ts, W2s, ty, tx, acc2);

    float acc[8][8];
#pragma unroll
    for (int r = 0; r < 8; r++) {
        unpk(acc[r][0], acc[r][1], acc2[r][0]);
        unpk(acc[r][2], acc[r][3], acc2[r][1]);
        unpk(acc[r][4], acc[r][5], acc2[r][2]);
        unpk(acc[r][6], acc[r][7], acc2[r][3]);
    }

    // thread-local segmented min over 8 consecutive sorted edges, then REDG.
    // b2 is NOT added here: min(m + b2) = min(m) + b2, applied in finalize.
    int cur = dstL[ty * 8];
    float mn[8];
#pragma unroll
    for (int c = 0; c < 8; c++) mn[c] = acc[0][c];
#pragma unroll
    for (int r = 1; r < 8; r++) {
        int d = dstL[ty * 8 + r];
        if (d == cur) {
#pragma unroll
            for (int c = 0; c < 8; c++) mn[c] = fminf(mn[c], acc[r][c]);
        } else {
            if (cur >= 0) {
                unsigned* base = aggr + (size_t)cur * H + tx * 8;
#pragma unroll
                for (int c = 0; c < 8; c++) atomicMin(base + c, fenc(mn[c]));
            }
            cur = d;
#pragma unroll
            for (int c = 0; c < 8; c++) mn[c] = acc[r][c];
        }
    }
    if (cur >= 0) {
        unsigned* base = aggr + (size_t)cur * H + tx * 8;
#pragma unroll
        for (int c = 0; c < 8; c++) atomicMin(base + c, fenc(mn[c]));
    }
}

// ---------------- host launch ----------------------------------------------
extern "C" void kernel_launch(void* const* d_in, const int* in_sizes, int n_in,
                              void* d_out, int out_size) {
    const float* x    = (const float*)d_in[0];
    const int*   ei   = (const int*)d_in[1];
    const float* ea   = (const float*)d_in[2];
    const float* embw = (const float*)d_in[3];
    const float* embb = (const float*)d_in[4];
    const float* mw1  = (const float*)d_in[5];
    const float* mb1  = (const float*)d_in[6];
    const float* mw2  = (const float*)d_in[7];
    const float* mb2  = (const float*)d_in[8];
    const float* uw1  = (const float*)d_in[9];
    const float* ub1  = (const float*)d_in[10];
    const float* uw2  = (const float*)d_in[11];
    const float* ub2  = (const float*)d_in[12];
    const float* fcw  = (const float*)d_in[13];
    const float* fcb  = (const float*)d_in[14];
    float* out = (float*)d_out;

    int N = in_sizes[0];        // NF = 1
    int E = in_sizes[2];        // EF = 1
    int L = in_sizes[6] / H;    // msg_b1 is [L, H]
    const int* src = ei;
    const int* dstp = ei + E;

    float* hbuf; float* Abuf; unsigned* aggr; int* cnt; int* cursor; int* perm;
    cudaGetSymbolAddress((void**)&hbuf, g_h);
    cudaGetSymbolAddress((void**)&Abuf, g_A);
    cudaGetSymbolAddress((void**)&aggr, g_aggr);
    cudaGetSymbolAddress((void**)&cnt, g_cnt);
    cudaGetSymbolAddress((void**)&cursor, g_cursor);
    cudaGetSymbolAddress((void**)&perm, g_perm);

    const size_t smE   = (4096 + 64 + 64 * 128) * 4 + 128 * 4 * 3;  // 50944 B
    const size_t sm64  = (64 * 64 + 64 * 128) * 4;                   // 49152 B
    const size_t sm128 = (128 * 64 + 128 * 128) * 4;                 // 98304 B
    cudaFuncSetAttribute(edge_kernel,
                         cudaFuncAttributeMaxDynamicSharedMemorySize, (int)smE);
    cudaFuncSetAttribute(node_gemm<64, false>,
                         cudaFuncAttributeMaxDynamicSharedMemorySize, (int)sm64);
    cudaFuncSetAttribute(node_gemm<128, true>,
                         cudaFuncAttributeMaxDynamicSharedMemorySize, (int)sm128);

    // embedding
    embed_kernel<<<(N * H + 255) / 256, 256>>>(x, embw, embb, hbuf, N);

    // counting sort of edges by dst (dst fixed across layers -> once per launch)
    cudaMemsetAsync(cnt, 0, (size_t)N * sizeof(int));
    count_kernel<<<(E + 255) / 256, 256>>>(dstp, cnt, E);
    scan_kernel<<<1, 1024>>>(cnt, cursor, N);
    scatter_kernel<<<(E + 255) / 256, 256>>>(dstp, cursor, perm, E);

    int nodeBlocks = (N + 127) / 128;
    int edgeBlocks = (E + 127) / 128;

    for (int l = 0; l < L; l++) {
        const float* w1 = mw1 + (size_t)l * (H + 1) * H;   // [65,64]
        // A = h @ W1[:64] + b1   (per-node hoist of the per-edge msg layer 1)
        node_gemm<64, false><<<nodeBlocks, 128, sm64>>>(
            hbuf, nullptr, w1, mb1 + (size_t)l * H, Abuf, N);
        // aggr identity = encoded +inf (0xFF bytes decode above enc(+inf))
        cudaMemsetAsync(aggr, 0xFF, (size_t)N * H * sizeof(unsigned));
        // fused: t=relu(A[src]+e*we); m=t@W2; segmented atomic min by dst
        edge_kernel<<<edgeBlocks, 128, smE>>>(
            Abuf, mw2 + (size_t)l * H * H, w1 + (size_t)H * H,
            src, dstp, ea, perm, aggr, E);
        // decode + add msg_b2; empty segments -> 0
        finalize_kernel<<<(N * H + 255) / 256, 256>>>(
            aggr, mb2 + (size_t)l * H, N);
        // update MLP: tmp = relu([h|aggr] @ uw1 + ub1); h = tmp @ uw2 + ub2
        node_gemm<128, true><<<nodeBlocks, 128, sm128>>>(
            hbuf, (const float*)aggr, uw1 + (size_t)l * 2 * H * H,
            ub1 + (size_t)l * H, Abuf, N);
        node_gemm<64, false><<<nodeBlocks, 128, sm64>>>(
            Abuf, nullptr, uw2 + (size_t)l * H * H, ub2 + (size_t)l * H,
            hbuf, N);
    }

    fc_kernel<<<(N + 255) / 256, 256>>>(hbuf, fcw, fcb, out, N);
}

// round 4
// speedup vs baseline: 1.1259x; 1.0852x over previous
#include <cuda_runtime.h>
#include <cuda_bf16.h>
#include <cstdint>

#define H 64
#define MAXN 100000
#define MAXE 1600000
#define MAXL 8

typedef unsigned long long u64;

// ---------------- device scratch (static: no dynamic allocation allowed) ----
__device__ float         g_h[(size_t)MAXN * H];
__device__ float         g_A[(size_t)MAXN * H];
__device__ unsigned int  g_aggr[(size_t)MAXN * H];
__device__ float         g_aggrF[(size_t)MAXN * H];
__device__ int           g_cnt[MAXN];
__device__ int           g_cursor[MAXN];
__device__ int           g_perm[MAXE];
__device__ __nv_bfloat16 g_Bh[MAXL * 64 * 72];  // per-layer W2^T hi, [n][72] rows
__device__ __nv_bfloat16 g_Bl[MAXL * 64 * 72];  // per-layer W2^T lo

// order-preserving float<->uint encoding for atomic min
__device__ __forceinline__ unsigned fenc(float f) {
    unsigned u = __float_as_uint(f);
    return (u & 0x80000000u) ? ~u : (u | 0x80000000u);
}
__device__ __forceinline__ float fdec(unsigned u) {
    return (u & 0x80000000u) ? __uint_as_float(u & 0x7FFFFFFFu)
                             : __uint_as_float(~u);
}

// -------- packed f32x2 helpers (node GEMMs) --------------------------------
__device__ __forceinline__ u64 pk_dup(float x) {
    u64 r;
    asm("mov.b64 %0, {%1,%1};" : "=l"(r) : "f"(x));
    return r;
}
__device__ __forceinline__ void fma2(u64& d, u64 a, u64 b) {
    asm("fma.rn.f32x2 %0, %1, %2, %3;" : "=l"(d) : "l"(a), "l"(b), "l"(d));
}
__device__ __forceinline__ void unpk(float& lo, float& hi, u64 v) {
    asm("mov.b64 {%0,%1}, %2;" : "=f"(lo), "=f"(hi) : "l"(v));
}

// -------- warp-mma plumbing (plain sm_80+ PTX: compiles for sm_103) --------
__device__ __forceinline__ uint32_t smem_u32(const void* p) {
    uint32_t a;
    asm("{ .reg .u64 t; cvta.to.shared.u64 t, %1; cvt.u32.u64 %0, t; }"
        : "=r"(a) : "l"(p));
    return a;
}
__device__ __forceinline__ void ldsm4(uint32_t (&r)[4], uint32_t addr) {
    asm volatile("ldmatrix.sync.aligned.m8n8.x4.shared.b16 {%0,%1,%2,%3}, [%4];"
                 : "=r"(r[0]), "=r"(r[1]), "=r"(r[2]), "=r"(r[3]) : "r"(addr));
}
__device__ __forceinline__ void ldsm2(uint32_t (&r)[2], uint32_t addr) {
    asm volatile("ldmatrix.sync.aligned.m8n8.x2.shared.b16 {%0,%1}, [%2];"
                 : "=r"(r[0]), "=r"(r[1]) : "r"(addr));
}
__device__ __forceinline__ void mma16816(float (&d)[4], const uint32_t (&a)[4],
                                         const uint32_t (&b)[2]) {
    asm volatile(
        "mma.sync.aligned.m16n8k16.row.col.f32.bf16.bf16.f32 "
        "{%0,%1,%2,%3}, {%4,%5,%6,%7}, {%8,%9}, {%0,%1,%2,%3};"
        : "+f"(d[0]), "+f"(d[1]), "+f"(d[2]), "+f"(d[3])
        : "r"(a[0]), "r"(a[1]), "r"(a[2]), "r"(a[3]), "r"(b[0]), "r"(b[1]));
}
// pack bf16(even)|bf16(odd)<<16  (element order matches memory layout)
__device__ __forceinline__ uint32_t cvt2(float odd, float even) {
    uint32_t d;
    asm("cvt.rn.bf16x2.f32 %0, %1, %2;" : "=r"(d) : "f"(odd), "f"(even));
    return d;
}

// ---------------- trivial elementwise kernels ------------------------------
__global__ void embed_kernel(const float* __restrict__ x,
                             const float* __restrict__ w,
                             const float* __restrict__ b,
                             float* __restrict__ h, int* __restrict__ cnt,
                             int n) {
    int i = blockIdx.x * blockDim.x + threadIdx.x;
    if (i < n) cnt[i] = 0;
    if (i < n * H) {
        int node = i >> 6, j = i & 63;
        h[i] = fmaf(x[node], w[j], b[j]);
    }
}

__global__ void count_kernel(const int* __restrict__ dst, int* cnt, int e) {
    int i = blockIdx.x * blockDim.x + threadIdx.x;
    if (i < e) atomicAdd(&cnt[dst[i]], 1);
}

// prefix scan of cnt + precompute per-layer bf16-split B = W2^T (stride 72)
__global__ void scan_prep_kernel(const int* __restrict__ cnt,
                                 int* __restrict__ cursor, int n,
                                 const float* __restrict__ mw2, int L) {
    int tid = threadIdx.x;
    int total = L * H * H;
    for (int i = tid; i < total; i += 1024) {
        int l = i >> 12, rem = i & 4095;
        int nn = rem >> 6, k = rem & 63;
        float w = mw2[(size_t)l * 4096 + k * 64 + nn];
        __nv_bfloat16 hi = __float2bfloat16(w);
        __nv_bfloat16 lo = __float2bfloat16(w - __bfloat162float(hi));
        size_t off = (size_t)l * (64 * 72) + nn * 72 + k;
        g_Bh[off] = hi;
        g_Bl[off] = lo;
    }
    __shared__ int s[1024];
    int chunk = (n + 1023) >> 10;
    int lo = tid * chunk;
    int hi = min(lo + chunk, n);
    int sum = 0;
    for (int i = lo; i < hi; i++) sum += cnt[i];
    s[tid] = sum;
    __syncthreads();
    for (int off = 1; off < 1024; off <<= 1) {
        int v = (tid >= off) ? s[tid - off] : 0;
        __syncthreads();
        s[tid] += v;
        __syncthreads();
    }
    int run = s[tid] - sum;
    for (int i = lo; i < hi; i++) { cursor[i] = run; run += cnt[i]; }
}

// scatter (build perm) + init aggr to encoded +inf
__global__ void scatter_kernel(const int* __restrict__ dst, int* cursor,
                               int* perm, unsigned* __restrict__ aggr,
                               int e, int nH4) {
    int i = blockIdx.x * blockDim.x + threadIdx.x;
    if (i < e) {
        int p = atomicAdd(&cursor[dst[i]], 1);
        perm[p] = i;
    }
    uint4 f = make_uint4(~0u, ~0u, ~0u, ~0u);
    for (int j = i; j < nH4; j += gridDim.x * blockDim.x)
        ((uint4*)aggr)[j] = f;
}

// decode aggr -> aggrF (+b2, empty->0), re-poison aggr for next layer
__global__ void finalize_kernel(unsigned* __restrict__ a,
                                float* __restrict__ af,
                                const float* __restrict__ b2, int n) {
    int i = blockIdx.x * blockDim.x + threadIdx.x;
    if (i < n * H) {
        unsigned u = a[i];
        af[i] = (u >= 0xFF800000u) ? 0.0f : (fdec(u) + b2[i & 63]);
        a[i] = 0xFFFFFFFFu;
    }
}

__global__ void fc_kernel(const float* __restrict__ h,
                          const float* __restrict__ fcw,
                          const float* __restrict__ fcb,
                          float* __restrict__ out, int n) {
    int i = blockIdx.x * blockDim.x + threadIdx.x;
    if (i >= n) return;
    const float4* h4 = (const float4*)(h + (size_t)i * H);
    const float4* w4 = (const float4*)fcw;
    float s = 0.f;
#pragma unroll
    for (int q = 0; q < 16; q++) {
        float4 a = h4[q], w = w4[q];
        s += a.x * w.x + a.y * w.y + a.z * w.z + a.w * w.w;
    }
    out[i] = s + fcb[0];
}

// -------- node GEMM (fp32 f32x2 path, proven in R2) ------------------------
template <int K>
__device__ __forceinline__ void gemm_body(const float* Xs, const float* Ws,
                                          int ty, int tx, u64 acc2[8][4]) {
    const float4* Xs4 = (const float4*)Xs;
#pragma unroll 4
    for (int k = 0; k < K; k++) {
        float4 a0 = Xs4[k * 32 + ty * 2];
        float4 a1 = Xs4[k * 32 + ty * 2 + 1];
        const ulonglong2* Wp = (const ulonglong2*)(Ws + k * 64 + tx * 8);
        ulonglong2 w01 = Wp[0];
        ulonglong2 w23 = Wp[1];
        u64 aa[8] = {pk_dup(a0.x), pk_dup(a0.y), pk_dup(a0.z), pk_dup(a0.w),
                     pk_dup(a1.x), pk_dup(a1.y), pk_dup(a1.z), pk_dup(a1.w)};
#pragma unroll
        for (int r = 0; r < 8; r++) {
            fma2(acc2[r][0], aa[r], w01.x);
            fma2(acc2[r][1], aa[r], w01.y);
            fma2(acc2[r][2], aa[r], w23.x);
            fma2(acc2[r][3], aa[r], w23.y);
        }
    }
}

template <int K, bool RELU>
__global__ void __launch_bounds__(128)
node_gemm(const float* __restrict__ X1, const float* __restrict__ X2,
          const float* __restrict__ W, const float* __restrict__ bias,
          float* __restrict__ C, int Nn) {
    extern __shared__ float sm[];
    float* Ws = sm;
    float* Xs = sm + K * 64;
    int tid = threadIdx.x;
    int n0 = blockIdx.x * 128;
    {
        const float4* W4 = (const float4*)W;
        float4* Ws4 = (float4*)Ws;
#pragma unroll
        for (int i = 0; i < K / 8; i++) Ws4[tid + i * 128] = W4[tid + i * 128];
    }
    {
        int n = min(n0 + tid, Nn - 1);
        const float4* X14 = (const float4*)(X1 + (size_t)n * H);
#pragma unroll
        for (int q = 0; q < 16; q++) {
            float4 v = X14[q];
            Xs[(4 * q + 0) * 128 + tid] = v.x;
            Xs[(4 * q + 1) * 128 + tid] = v.y;
            Xs[(4 * q + 2) * 128 + tid] = v.z;
            Xs[(4 * q + 3) * 128 + tid] = v.w;
        }
        if (K == 128) {
            const float4* X24 = (const float4*)(X2 + (size_t)n * H);
#pragma unroll
            for (int q = 0; q < 16; q++) {
                float4 v = X24[q];
                Xs[(64 + 4 * q + 0) * 128 + tid] = v.x;
                Xs[(64 + 4 * q + 1) * 128 + tid] = v.y;
                Xs[(64 + 4 * q + 2) * 128 + tid] = v.z;
                Xs[(64 + 4 * q + 3) * 128 + tid] = v.w;
            }
        }
    }
    __syncthreads();
    int ty = tid >> 3, tx = tid & 7;
    u64 acc2[8][4];
#pragma unroll
    for (int r = 0; r < 8; r++)
#pragma unroll
        for (int c = 0; c < 4; c++) acc2[r][c] = 0ull;
    gemm_body<K>(Xs, Ws, ty, tx, acc2);
    float bb[8];
#pragma unroll
    for (int c = 0; c < 8; c++) bb[c] = bias[tx * 8 + c];
#pragma unroll
    for (int r = 0; r < 8; r++) {
        int n = n0 + ty * 8 + r;
        if (n < Nn) {
            float o[8];
            unpk(o[0], o[1], acc2[r][0]);
            unpk(o[2], o[3], acc2[r][1]);
            unpk(o[4], o[5], acc2[r][2]);
            unpk(o[6], o[7], acc2[r][3]);
            float4 o0, o1;
            o0.x = o[0] + bb[0]; o0.y = o[1] + bb[1];
            o0.z = o[2] + bb[2]; o0.w = o[3] + bb[3];
            o1.x = o[4] + bb[4]; o1.y = o[5] + bb[5];
            o1.z = o[6] + bb[6]; o1.w = o[7] + bb[7];
            if (RELU) {
                o0.x = fmaxf(o0.x, 0.f); o0.y = fmaxf(o0.y, 0.f);
                o0.z = fmaxf(o0.z, 0.f); o0.w = fmaxf(o0.w, 0.f);
                o1.x = fmaxf(o1.x, 0.f); o1.y = fmaxf(o1.y, 0.f);
                o1.z = fmaxf(o1.z, 0.f); o1.w = fmaxf(o1.w, 0.f);
            }
            float4* C4 = (float4*)(C + (size_t)n * H);
            C4[tx * 2] = o0;
            C4[tx * 2 + 1] = o1;
        }
    }
}

// ---------------- HMMA edge kernel (persistent, bf16x3 split) --------------
// Per 128-edge tile: T = relu(A[src]+ev*we) -> Th/Tl bf16 rows (stride 72);
// D[128,64] = Th@Bh^T + Tl@Bh^T + Th@Bl^T via mma.sync m16n8k16 (fp32 acc);
// D staged to XOR-swizzled SMEM -> segmented min by sorted dst -> atomicMin.
#define TH_OFF   0            // 128 x 72 bf16 = 18432 B (reused as Ds 32768 B)
#define TL_OFF   18432        // 128 x 72 bf16
#define BH_OFF   36864        // 64 x 72 bf16 = 9216 B
#define BL_OFF   46080        // 64 x 72 bf16
#define WES_OFF  55296        // 64 f32
#define DST_OFF  55552        // 128 int
#define SMEM_EDGE 56320

__global__ void __launch_bounds__(128, 4)
edge_mma_kernel(const float* __restrict__ Ag, const int* __restrict__ src,
                const int* __restrict__ dstp, const float* __restrict__ ea,
                const int* __restrict__ perm, const float* __restrict__ weg,
                const __nv_bfloat16* __restrict__ Bh_g,
                const __nv_bfloat16* __restrict__ Bl_g,
                unsigned* __restrict__ aggr, int E, int ntiles) {
    extern __shared__ char smc[];
    uint32_t sb = smem_u32(smc);
    int tid = threadIdx.x;
    int lane = tid & 31;
    int wid = tid >> 5;

    // one-time: copy B hi/lo (576 uint4 each) + we into smem
    {
        const uint4* s4 = (const uint4*)Bh_g;
        uint4* d4 = (uint4*)(smc + BH_OFF);
        for (int i = tid; i < 576; i += 128) d4[i] = s4[i];
        s4 = (const uint4*)Bl_g;
        d4 = (uint4*)(smc + BL_OFF);
        for (int i = tid; i < 576; i += 128) d4[i] = s4[i];
        if (tid < 64) ((float*)(smc + WES_OFF))[tid] = weg[tid];
    }
    __syncthreads();

    const float* wes = (const float*)(smc + WES_OFF);
    int* dstL = (int*)(smc + DST_OFF);
    float* Ds = (float*)smc;   // overlays Th+Tl after mma reads complete

    int m0 = wid * 32;
    // per-lane ldmatrix address components (bytes)
    uint32_t aRow = (lane & 7) + 8u * ((lane >> 3) & 1);
    uint32_t aKoff = 16u * (lane >> 4);
    uint32_t bRow = lane & 7;
    uint32_t bKoff = 16u * ((lane >> 3) & 1);

    for (int tile = blockIdx.x; tile < ntiles; tile += gridDim.x) {
        // ---- gather + relu + bf16 split -> Th/Tl rows (144B stride) ----
        {
            int slot = tile * 128 + tid;
            int eidx = perm[min(slot, E - 1)];
            int s = src[eidx];
            float ev = ea[eidx];
            dstL[tid] = (slot < E) ? dstp[eidx] : -1;
            const float4* A4 = (const float4*)(Ag + (size_t)s * H);
            char* thRow = smc + TH_OFF + tid * 144;
            char* tlRow = smc + TL_OFF + tid * 144;
#pragma unroll
            for (int q = 0; q < 8; q++) {
                float4 a0 = A4[2 * q], a1 = A4[2 * q + 1];
                float v[8];
                v[0] = fmaxf(fmaf(ev, wes[q * 8 + 0], a0.x), 0.f);
                v[1] = fmaxf(fmaf(ev, wes[q * 8 + 1], a0.y), 0.f);
                v[2] = fmaxf(fmaf(ev, wes[q * 8 + 2], a0.z), 0.f);
                v[3] = fmaxf(fmaf(ev, wes[q * 8 + 3], a0.w), 0.f);
                v[4] = fmaxf(fmaf(ev, wes[q * 8 + 4], a1.x), 0.f);
                v[5] = fmaxf(fmaf(ev, wes[q * 8 + 5], a1.y), 0.f);
                v[6] = fmaxf(fmaf(ev, wes[q * 8 + 6], a1.z), 0.f);
                v[7] = fmaxf(fmaf(ev, wes[q * 8 + 7], a1.w), 0.f);
                uint32_t hp[4], lp[4];
#pragma unroll
                for (int j = 0; j < 4; j++) {
                    uint32_t h2 = cvt2(v[2 * j + 1], v[2 * j]);
                    float he = __uint_as_float(h2 << 16);
                    float ho = __uint_as_float(h2 & 0xFFFF0000u);
                    hp[j] = h2;
                    lp[j] = cvt2(v[2 * j + 1] - ho, v[2 * j] - he);
                }
                *(uint4*)(thRow + q * 16) = make_uint4(hp[0], hp[1], hp[2], hp[3]);
                *(uint4*)(tlRow + q * 16) = make_uint4(lp[0], lp[1], lp[2], lp[3]);
            }
        }
        __syncthreads();

        // ---- warp MMA: D slice rows m0..m0+31, 3 terms x 4 k-steps ----
        float acc[2][8][4];
#pragma unroll
        for (int mt = 0; mt < 2; mt++)
#pragma unroll
            for (int nt = 0; nt < 8; nt++)
#pragma unroll
                for (int c = 0; c < 4; c++) acc[mt][nt][c] = 0.f;

#pragma unroll
        for (int t = 0; t < 3; t++) {
            uint32_t Ab = sb + ((t == 1) ? TL_OFF : TH_OFF);
            uint32_t Bb = sb + ((t == 2) ? BL_OFF : BH_OFF);
#pragma unroll
            for (int ks = 0; ks < 4; ks++) {
                uint32_t a0[4], a1[4];
                ldsm4(a0, Ab + 144u * (m0 + aRow) + 32u * ks + aKoff);
                ldsm4(a1, Ab + 144u * (m0 + 16 + aRow) + 32u * ks + aKoff);
#pragma unroll
                for (int nt = 0; nt < 8; nt++) {
                    uint32_t b[2];
                    ldsm2(b, Bb + 144u * (nt * 8 + bRow) + 32u * ks + bKoff);
                    mma16816(acc[0][nt], a0, b);
                    mma16816(acc[1][nt], a1, b);
                }
            }
        }
        __syncthreads();   // all Th/Tl reads done before Ds overlay writes

        // ---- stage D to swizzled SMEM: float4 slot = e*16 + (c4^(e&15)) ----
#pragma unroll
        for (int mt = 0; mt < 2; mt++) {
            int eb = m0 + mt * 16 + (lane >> 2);
            int h2 = lane & 1;
            int c4b = (lane & 3) >> 1;
#pragma unroll
            for (int nt = 0; nt < 8; nt++) {
                int c4 = nt * 2 + c4b;
                float2 v0 = make_float2(acc[mt][nt][0], acc[mt][nt][1]);
                float2 v1 = make_float2(acc[mt][nt][2], acc[mt][nt][3]);
                int e0 = eb, e1 = eb + 8;
                ((float2*)(Ds + (e0 * 16 + (c4 ^ (e0 & 15))) * 4))[h2] = v0;
                ((float2*)(Ds + (e1 * 16 + (c4 ^ (e1 & 15))) * 4))[h2] = v1;
            }
        }
        __syncthreads();

        // ---- epilogue: segmented min over 8 sorted edges, atomicMin ----
        {
            const float4* Ds4 = (const float4*)Ds;
            int ty = tid >> 3, tx = tid & 7;
            int cur = -2;
            float4 mA, mB;
#pragma unroll
            for (int r = 0; r < 8; r++) {
                int e = ty * 8 + r;
                int d = dstL[e];
                float4 a = Ds4[e * 16 + (tx ^ (e & 15))];
                float4 b = Ds4[e * 16 + ((8 + tx) ^ (e & 15))];
                if (r == 0 || d != cur) {
                    if (r > 0 && cur >= 0) {
                        unsigned* p0 = aggr + (size_t)cur * H + tx * 4;
                        atomicMin(p0 + 0, fenc(mA.x));
                        atomicMin(p0 + 1, fenc(mA.y));
                        atomicMin(p0 + 2, fenc(mA.z));
                        atomicMin(p0 + 3, fenc(mA.w));
                        unsigned* p1 = p0 + 32;
                        atomicMin(p1 + 0, fenc(mB.x));
                        atomicMin(p1 + 1, fenc(mB.y));
                        atomicMin(p1 + 2, fenc(mB.z));
                        atomicMin(p1 + 3, fenc(mB.w));
                    }
                    cur = d;
                    mA = a; mB = b;
                } else {
                    mA.x = fminf(mA.x, a.x); mA.y = fminf(mA.y, a.y);
                    mA.z = fminf(mA.z, a.z); mA.w = fminf(mA.w, a.w);
                    mB.x = fminf(mB.x, b.x); mB.y = fminf(mB.y, b.y);
                    mB.z = fminf(mB.z, b.z); mB.w = fminf(mB.w, b.w);
                }
            }
            if (cur >= 0) {
                unsigned* p0 = aggr + (size_t)cur * H + tx * 4;
                atomicMin(p0 + 0, fenc(mA.x));
                atomicMin(p0 + 1, fenc(mA.y));
                atomicMin(p0 + 2, fenc(mA.z));
                atomicMin(p0 + 3, fenc(mA.w));
                unsigned* p1 = p0 + 32;
                atomicMin(p1 + 0, fenc(mB.x));
                atomicMin(p1 + 1, fenc(mB.y));
                atomicMin(p1 + 2, fenc(mB.z));
                atomicMin(p1 + 3, fenc(mB.w));
            }
        }
        __syncthreads();   // Ds/dstL dead before next tile's writes
    }
}

// ---------------- host launch ----------------------------------------------
extern "C" void kernel_launch(void* const* d_in, const int* in_sizes, int n_in,
                              void* d_out, int out_size) {
    const float* x    = (const float*)d_in[0];
    const int*   ei   = (const int*)d_in[1];
    const float* ea   = (const float*)d_in[2];
    const float* embw = (const float*)d_in[3];
    const float* embb = (const float*)d_in[4];
    const float* mw1  = (const float*)d_in[5];
    const float* mb1  = (const float*)d_in[6];
    const float* mw2  = (const float*)d_in[7];
    const float* mb2  = (const float*)d_in[8];
    const float* uw1  = (const float*)d_in[9];
    const float* ub1  = (const float*)d_in[10];
    const float* uw2  = (const float*)d_in[11];
    const float* ub2  = (const float*)d_in[12];
    const float* fcw  = (const float*)d_in[13];
    const float* fcb  = (const float*)d_in[14];
    float* out = (float*)d_out;

    int N = in_sizes[0];
    int E = in_sizes[2];
    int L = in_sizes[6] / H;
    const int* src = ei;
    const int* dstp = ei + E;

    float* hbuf; float* Abuf; unsigned* aggr; float* aggrF;
    int* cnt; int* cursor; int* perm;
    __nv_bfloat16* Bh; __nv_bfloat16* Bl;
    cudaGetSymbolAddress((void**)&hbuf, g_h);
    cudaGetSymbolAddress((void**)&Abuf, g_A);
    cudaGetSymbolAddress((void**)&aggr, g_aggr);
    cudaGetSymbolAddress((void**)&aggrF, g_aggrF);
    cudaGetSymbolAddress((void**)&cnt, g_cnt);
    cudaGetSymbolAddress((void**)&cursor, g_cursor);
    cudaGetSymbolAddress((void**)&perm, g_perm);
    cudaGetSymbolAddress((void**)&Bh, g_Bh);
    cudaGetSymbolAddress((void**)&Bl, g_Bl);

    const size_t sm64  = (64 * 64 + 64 * 128) * 4;
    const size_t sm128 = (128 * 64 + 128 * 128) * 4;
    cudaFuncSetAttribute(edge_mma_kernel,
                         cudaFuncAttributeMaxDynamicSharedMemorySize, SMEM_EDGE);
    cudaFuncSetAttribute(node_gemm<64, false>,
                         cudaFuncAttributeMaxDynamicSharedMemorySize, (int)sm64);
    cudaFuncSetAttribute(node_gemm<128, true>,
                         cudaFuncAttributeMaxDynamicSharedMemorySize, (int)sm128);

    int ntiles = (E + 127) / 128;
    int edgeGrid = 148 * 4;
    if (edgeGrid > ntiles) edgeGrid = ntiles;
    int nodeBlocks = (N + 127) / 128;

    // embedding (+ zero cnt)
    embed_kernel<<<(N * H + 255) / 256, 256>>>(x, embw, embb, hbuf, cnt, N);
    // counting sort by dst (+ B split prep, + aggr init)
    count_kernel<<<(E + 255) / 256, 256>>>(dstp, cnt, E);
    scan_prep_kernel<<<1, 1024>>>(cnt, cursor, N, mw2, L);
    scatter_kernel<<<(E + 255) / 256, 256>>>(dstp, cursor, perm, aggr, E,
                                             N * H / 4);

    for (int l = 0; l < L; l++) {
        const float* w1 = mw1 + (size_t)l * (H + 1) * H;   // [65,64]
        // A = h @ W1[:64] + b1  (per-node hoist of per-edge msg layer 1)
        node_gemm<64, false><<<nodeBlocks, 128, sm64>>>(
            hbuf, nullptr, w1, mb1 + (size_t)l * H, Abuf, N);
        // tensor-pipe edge message + scatter-min
        edge_mma_kernel<<<edgeGrid, 128, SMEM_EDGE>>>(
            Abuf, src, dstp, ea, perm, w1 + (size_t)H * H,
            Bh + (size_t)l * (64 * 72), Bl + (size_t)l * (64 * 72),
            aggr, E, ntiles);
        // decode + b2, empty->0, re-poison aggr
        finalize_kernel<<<(N * H + 255) / 256, 256>>>(
            aggr, aggrF, mb2 + (size_t)l * H, N);
        // update MLP
        node_gemm<128, true><<<nodeBlocks, 128, sm128>>>(
            hbuf, aggrF, uw1 + (size_t)l * 2 * H * H, ub1 + (size_t)l * H,
            Abuf, N);
        node_gemm<64, false><<<nodeBlocks, 128, sm64>>>(
            Abuf, nullptr, uw2 + (size_t)l * H * H, ub2 + (size_t)l * H,
            hbuf, N);
    }

    fc_kernel<<<(N + 255) / 256, 256>>>(hbuf, fcw, fcb, out, N);
}

// round 5
// speedup vs baseline: 1.4598x; 1.2967x over previous
#include <cuda_runtime.h>
#include <cuda_bf16.h>
#include <cuda_fp16.h>
#include <cstdint>

#define H 64
#define MAXN 100000
#define MAXE 1600000
#define MAXL 8

typedef unsigned long long u64;

// ---------------- device scratch (static: no dynamic allocation allowed) ----
__device__ float         g_h[(size_t)MAXN * H];
__device__ float         g_A[(size_t)MAXN * H];
__device__ unsigned int  g_aggr[(size_t)MAXN * H];
__device__ int           g_cnt[MAXN];
__device__ int           g_cursor[MAXN];
__device__ int           g_perm[MAXE];
__device__ __half        g_Bh[MAXL * 64 * 72];  // per-layer W2^T fp16, [n][72] rows

// order-preserving float<->uint encoding for atomic min
__device__ __forceinline__ unsigned fenc(float f) {
    unsigned u = __float_as_uint(f);
    return (u & 0x80000000u) ? ~u : (u | 0x80000000u);
}
__device__ __forceinline__ float fdec(unsigned u) {
    return (u & 0x80000000u) ? __uint_as_float(u & 0x7FFFFFFFu)
                             : __uint_as_float(~u);
}

// -------- packed f32x2 helpers (node GEMMs) --------------------------------
__device__ __forceinline__ u64 pk_dup(float x) {
    u64 r;
    asm("mov.b64 %0, {%1,%1};" : "=l"(r) : "f"(x));
    return r;
}
__device__ __forceinline__ void fma2(u64& d, u64 a, u64 b) {
    asm("fma.rn.f32x2 %0, %1, %2, %3;" : "=l"(d) : "l"(a), "l"(b), "l"(d));
}
__device__ __forceinline__ void unpk(float& lo, float& hi, u64 v) {
    asm("mov.b64 {%0,%1}, %2;" : "=f"(lo), "=f"(hi) : "l"(v));
}

// -------- warp-mma plumbing (plain sm_80+ PTX) -----------------------------
__device__ __forceinline__ uint32_t smem_u32(const void* p) {
    uint32_t a;
    asm("{ .reg .u64 t; cvta.to.shared.u64 t, %1; cvt.u32.u64 %0, t; }"
        : "=r"(a) : "l"(p));
    return a;
}
__device__ __forceinline__ void ldsm4(uint32_t (&r)[4], uint32_t addr) {
    asm volatile("ldmatrix.sync.aligned.m8n8.x4.shared.b16 {%0,%1,%2,%3}, [%4];"
                 : "=r"(r[0]), "=r"(r[1]), "=r"(r[2]), "=r"(r[3]) : "r"(addr));
}
__device__ __forceinline__ void mma16816h(float (&d)[4], const uint32_t (&a)[4],
                                          uint32_t b0, uint32_t b1) {
    asm volatile(
        "mma.sync.aligned.m16n8k16.row.col.f32.f16.f16.f32 "
        "{%0,%1,%2,%3}, {%4,%5,%6,%7}, {%8,%9}, {%0,%1,%2,%3};"
        : "+f"(d[0]), "+f"(d[1]), "+f"(d[2]), "+f"(d[3])
        : "r"(a[0]), "r"(a[1]), "r"(a[2]), "r"(a[3]), "r"(b0), "r"(b1));
}
// pack f16(even)|f16(odd)<<16 (same operand convention as the proven bf16 path)
__device__ __forceinline__ uint32_t cvt2h(float odd, float even) {
    uint32_t d;
    asm("cvt.rn.f16x2.f32 %0, %1, %2;" : "=r"(d) : "f"(odd), "f"(even));
    return d;
}
__device__ __forceinline__ float2 h22f2(uint32_t h) {
    __half2 hh = *(__half2*)&h;
    return __half22float2(hh);
}

// ---------------- trivial elementwise kernels ------------------------------
__global__ void embed_kernel(const float* __restrict__ x,
                             const float* __restrict__ w,
                             const float* __restrict__ b,
                             float* __restrict__ h, int* __restrict__ cnt,
                             int n) {
    int i = blockIdx.x * blockDim.x + threadIdx.x;
    if (i < n) cnt[i] = 0;
    if (i < n * H) {
        int node = i >> 6, j = i & 63;
        h[i] = fmaf(x[node], w[j], b[j]);
    }
}

__global__ void count_kernel(const int* __restrict__ dst, int* cnt, int e) {
    int i = blockIdx.x * blockDim.x + threadIdx.x;
    if (i < e) atomicAdd(&cnt[dst[i]], 1);
}

// prefix scan of cnt + precompute per-layer fp16 B = W2^T (stride 72)
__global__ void scan_prep_kernel(const int* __restrict__ cnt,
                                 int* __restrict__ cursor, int n,
                                 const float* __restrict__ mw2, int L) {
    int tid = threadIdx.x;
    int total = L * H * H;
    for (int i = tid; i < total; i += 1024) {
        int l = i >> 12, rem = i & 4095;
        int nn = rem >> 6, k = rem & 63;
        float w = mw2[(size_t)l * 4096 + k * 64 + nn];
        g_Bh[(size_t)l * (64 * 72) + nn * 72 + k] = __float2half_rn(w);
    }
    __shared__ int s[1024];
    int chunk = (n + 1023) >> 10;
    int lo = tid * chunk;
    int hi = min(lo + chunk, n);
    int sum = 0;
    for (int i = lo; i < hi; i++) sum += cnt[i];
    s[tid] = sum;
    __syncthreads();
    for (int off = 1; off < 1024; off <<= 1) {
        int v = (tid >= off) ? s[tid - off] : 0;
        __syncthreads();
        s[tid] += v;
        __syncthreads();
    }
    int run = s[tid] - sum;
    for (int i = lo; i < hi; i++) { cursor[i] = run; run += cnt[i]; }
}

// scatter (build perm) + init aggr to encoded +inf
__global__ void scatter_kernel(const int* __restrict__ dst, int* cursor,
                               int* perm, unsigned* __restrict__ aggr,
                               int e, int nH4) {
    int i = blockIdx.x * blockDim.x + threadIdx.x;
    if (i < e) {
        int p = atomicAdd(&cursor[dst[i]], 1);
        perm[p] = i;
    }
    uint4 f = make_uint4(~0u, ~0u, ~0u, ~0u);
    for (int j = i; j < nH4; j += gridDim.x * blockDim.x)
        ((uint4*)aggr)[j] = f;
}

__global__ void fc_kernel(const float* __restrict__ h,
                          const float* __restrict__ fcw,
                          const float* __restrict__ fcb,
                          float* __restrict__ out, int n) {
    int i = blockIdx.x * blockDim.x + threadIdx.x;
    if (i >= n) return;
    const float4* h4 = (const float4*)(h + (size_t)i * H);
    const float4* w4 = (const float4*)fcw;
    float s = 0.f;
#pragma unroll
    for (int q = 0; q < 16; q++) {
        float4 a = h4[q], w = w4[q];
        s += a.x * w.x + a.y * w.y + a.z * w.z + a.w * w.w;
    }
    out[i] = s + fcb[0];
}

// -------- node GEMM (fp32 f32x2 path; DECODE fuses aggr finalize) ----------
template <int K>
__device__ __forceinline__ void gemm_body(const float* Xs, const float* Ws,
                                          int ty, int tx, u64 acc2[8][4]) {
    const float4* Xs4 = (const float4*)Xs;
#pragma unroll 4
    for (int k = 0; k < K; k++) {
        float4 a0 = Xs4[k * 32 + ty * 2];
        float4 a1 = Xs4[k * 32 + ty * 2 + 1];
        const ulonglong2* Wp = (const ulonglong2*)(Ws + k * 64 + tx * 8);
        ulonglong2 w01 = Wp[0];
        ulonglong2 w23 = Wp[1];
        u64 aa[8] = {pk_dup(a0.x), pk_dup(a0.y), pk_dup(a0.z), pk_dup(a0.w),
                     pk_dup(a1.x), pk_dup(a1.y), pk_dup(a1.z), pk_dup(a1.w)};
#pragma unroll
        for (int r = 0; r < 8; r++) {
            fma2(acc2[r][0], aa[r], w01.x);
            fma2(acc2[r][1], aa[r], w01.y);
            fma2(acc2[r][2], aa[r], w23.x);
            fma2(acc2[r][3], aa[r], w23.y);
        }
    }
}

template <int K, bool RELU, bool DECODE>
__global__ void __launch_bounds__(128)
node_gemm(const float* __restrict__ X1, const void* __restrict__ X2p,
          const float* __restrict__ W, const float* __restrict__ bias,
          float* __restrict__ C, int Nn,
          const float* __restrict__ b2g, unsigned* __restrict__ aggrw) {
    extern __shared__ float sm[];
    float* Ws = sm;
    float* Xs = sm + K * 64;
    float* b2s = sm + K * 64 + K * 128;   // 64 floats (DECODE only)
    int tid = threadIdx.x;
    int n0 = blockIdx.x * 128;
    {
        const float4* W4 = (const float4*)W;
        float4* Ws4 = (float4*)Ws;
#pragma unroll
        for (int i = 0; i < K / 8; i++) Ws4[tid + i * 128] = W4[tid + i * 128];
    }
    int n = min(n0 + tid, Nn - 1);
    {
        const float4* X14 = (const float4*)(X1 + (size_t)n * H);
#pragma unroll
        for (int q = 0; q < 16; q++) {
            float4 v = X14[q];
            Xs[(4 * q + 0) * 128 + tid] = v.x;
            Xs[(4 * q + 1) * 128 + tid] = v.y;
            Xs[(4 * q + 2) * 128 + tid] = v.z;
            Xs[(4 * q + 3) * 128 + tid] = v.w;
        }
    }
    if (DECODE) {
        if (tid < 64) b2s[tid] = b2g[tid];
        __syncthreads();
    }
    if (K == 128) {
        if (DECODE) {
            const uint4* X24 = (const uint4*)((const unsigned*)X2p +
                                              (size_t)n * H);
#pragma unroll
            for (int q = 0; q < 16; q++) {
                uint4 u = X24[q];
                float4 v;
                v.x = (u.x >= 0xFF800000u) ? 0.f : (fdec(u.x) + b2s[4 * q + 0]);
                v.y = (u.y >= 0xFF800000u) ? 0.f : (fdec(u.y) + b2s[4 * q + 1]);
                v.z = (u.z >= 0xFF800000u) ? 0.f : (fdec(u.z) + b2s[4 * q + 2]);
                v.w = (u.w >= 0xFF800000u) ? 0.f : (fdec(u.w) + b2s[4 * q + 3]);
                Xs[(64 + 4 * q + 0) * 128 + tid] = v.x;
                Xs[(64 + 4 * q + 1) * 128 + tid] = v.y;
                Xs[(64 + 4 * q + 2) * 128 + tid] = v.z;
                Xs[(64 + 4 * q + 3) * 128 + tid] = v.w;
            }
            // re-poison aggr for next layer (owner thread only; safe at tail)
            if (n0 + tid < Nn) {
                uint4 p = make_uint4(~0u, ~0u, ~0u, ~0u);
                uint4* A4 = (uint4*)(aggrw + (size_t)n * H);
#pragma unroll
                for (int q = 0; q < 16; q++) A4[q] = p;
            }
        } else {
            const float4* X24 = (const float4*)((const float*)X2p +
                                                (size_t)n * H);
#pragma unroll
            for (int q = 0; q < 16; q++) {
                float4 v = X24[q];
                Xs[(64 + 4 * q + 0) * 128 + tid] = v.x;
                Xs[(64 + 4 * q + 1) * 128 + tid] = v.y;
                Xs[(64 + 4 * q + 2) * 128 + tid] = v.z;
                Xs[(64 + 4 * q + 3) * 128 + tid] = v.w;
            }
        }
    }
    __syncthreads();
    int ty = tid >> 3, tx = tid & 7;
    u64 acc2[8][4];
#pragma unroll
    for (int r = 0; r < 8; r++)
#pragma unroll
        for (int c = 0; c < 4; c++) acc2[r][c] = 0ull;
    gemm_body<K>(Xs, Ws, ty, tx, acc2);
    float bb[8];
#pragma unroll
    for (int c = 0; c < 8; c++) bb[c] = bias[tx * 8 + c];
#pragma unroll
    for (int r = 0; r < 8; r++) {
        int nr = n0 + ty * 8 + r;
        if (nr < Nn) {
            float o[8];
            unpk(o[0], o[1], acc2[r][0]);
            unpk(o[2], o[3], acc2[r][1]);
            unpk(o[4], o[5], acc2[r][2]);
            unpk(o[6], o[7], acc2[r][3]);
            float4 o0, o1;
            o0.x = o[0] + bb[0]; o0.y = o[1] + bb[1];
            o0.z = o[2] + bb[2]; o0.w = o[3] + bb[3];
            o1.x = o[4] + bb[4]; o1.y = o[5] + bb[5];
            o1.z = o[6] + bb[6]; o1.w = o[7] + bb[7];
            if (RELU) {
                o0.x = fmaxf(o0.x, 0.f); o0.y = fmaxf(o0.y, 0.f);
                o0.z = fmaxf(o0.z, 0.f); o0.w = fmaxf(o0.w, 0.f);
                o1.x = fmaxf(o1.x, 0.f); o1.y = fmaxf(o1.y, 0.f);
                o1.z = fmaxf(o1.z, 0.f); o1.w = fmaxf(o1.w, 0.f);
            }
            float4* C4 = (float4*)(C + (size_t)nr * H);
            C4[tx * 2] = o0;
            C4[tx * 2 + 1] = o1;
        }
    }
}

// ---------------- HMMA edge kernel (persistent, fp16 2-term split) ---------
// Per 128-edge tile: T = relu(A[src]+ev*we) -> Th/Tl fp16 rows (stride 72);
// D[128,64] = Th@Bh^T + Tl@Bh^T  (B single fp16; dropped T@Bl ~ 2^-11);
// D staged to XOR-swizzled SMEM -> segmented min by sorted dst -> atomicMin.
#define TH_OFF   0            // 128 x 72 f16 = 18432 B (Ds overlay: 32768 B)
#define TL_OFF   18432        // 128 x 72 f16
#define BH_OFF   36864        // 64 x 72 f16 = 9216 B
#define WES_OFF  46080        // 64 f32
#define DST_OFF  46336        // 128 int
#define SMEM_EDGE 46848

__global__ void __launch_bounds__(128, 4)
edge_mma_kernel(const float* __restrict__ Ag, const int* __restrict__ src,
                const int* __restrict__ dstp, const float* __restrict__ ea,
                const int* __restrict__ perm, const float* __restrict__ weg,
                const __half* __restrict__ Bh_g,
                unsigned* __restrict__ aggr, int E, int ntiles) {
    extern __shared__ char smc[];
    uint32_t sb = smem_u32(smc);
    int tid = threadIdx.x;
    int lane = tid & 31;
    int wid = tid >> 5;

    // one-time: copy B (576 uint4) + we into smem
    {
        const uint4* s4 = (const uint4*)Bh_g;
        uint4* d4 = (uint4*)(smc + BH_OFF);
        for (int i = tid; i < 576; i += 128) d4[i] = s4[i];
        if (tid < 64) ((float*)(smc + WES_OFF))[tid] = weg[tid];
    }
    __syncthreads();

    const float* wes = (const float*)(smc + WES_OFF);
    int* dstL = (int*)(smc + DST_OFF);
    float* Ds = (float*)smc;   // overlays Th+Tl after mma reads complete

    int m0 = wid * 32;
    // ldmatrix lane-address components
    uint32_t aRow = (lane & 7) + 8u * ((lane >> 3) & 1);
    uint32_t aKoff = 16u * (lane >> 4);
    uint32_t bBase = 144u * (8u * ((lane >> 4) & 1) + (lane & 7)) +
                     16u * ((lane >> 3) & 1);

    for (int tile = blockIdx.x; tile < ntiles; tile += gridDim.x) {
        // ---- gather + relu + fp16 split -> Th/Tl rows (144B stride) ----
        {
            int slot = tile * 128 + tid;
            int eidx = perm[min(slot, E - 1)];
            int s = src[eidx];
            float ev = ea[eidx];
            dstL[tid] = (slot < E) ? dstp[eidx] : -1;
            const float4* A4 = (const float4*)(Ag + (size_t)s * H);
            char* thRow = smc + TH_OFF + tid * 144;
            char* tlRow = smc + TL_OFF + tid * 144;
#pragma unroll
            for (int q = 0; q < 8; q++) {
                float4 a0 = A4[2 * q], a1 = A4[2 * q + 1];
                float v[8];
                v[0] = fmaxf(fmaf(ev, wes[q * 8 + 0], a0.x), 0.f);
                v[1] = fmaxf(fmaf(ev, wes[q * 8 + 1], a0.y), 0.f);
                v[2] = fmaxf(fmaf(ev, wes[q * 8 + 2], a0.z), 0.f);
                v[3] = fmaxf(fmaf(ev, wes[q * 8 + 3], a0.w), 0.f);
                v[4] = fmaxf(fmaf(ev, wes[q * 8 + 4], a1.x), 0.f);
                v[5] = fmaxf(fmaf(ev, wes[q * 8 + 5], a1.y), 0.f);
                v[6] = fmaxf(fmaf(ev, wes[q * 8 + 6], a1.z), 0.f);
                v[7] = fmaxf(fmaf(ev, wes[q * 8 + 7], a1.w), 0.f);
                uint32_t hp[4], lp[4];
#pragma unroll
                for (int j = 0; j < 4; j++) {
                    float e = v[2 * j], o = v[2 * j + 1];
                    uint32_t h2 = cvt2h(o, e);
                    float2 bk = h22f2(h2);
                    hp[j] = h2;
                    lp[j] = cvt2h(o - bk.y, e - bk.x);
                }
                *(uint4*)(thRow + q * 16) = make_uint4(hp[0], hp[1], hp[2], hp[3]);
                *(uint4*)(tlRow + q * 16) = make_uint4(lp[0], lp[1], lp[2], lp[3]);
            }
        }
        __syncthreads();

        // ---- warp MMA: rows m0..m0+31, 2 terms x 4 k-steps ----
        float acc[2][8][4];
#pragma unroll
        for (int mt = 0; mt < 2; mt++)
#pragma unroll
            for (int nt = 0; nt < 8; nt++)
#pragma unroll
                for (int c = 0; c < 4; c++) acc[mt][nt][c] = 0.f;

#pragma unroll
        for (int ks = 0; ks < 4; ks++) {
            uint32_t ah0[4], ah1[4], al0[4], al1[4];
            ldsm4(ah0, sb + TH_OFF + 144u * (m0 + aRow) + 32u * ks + aKoff);
            ldsm4(ah1, sb + TH_OFF + 144u * (m0 + 16 + aRow) + 32u * ks + aKoff);
            ldsm4(al0, sb + TL_OFF + 144u * (m0 + aRow) + 32u * ks + aKoff);
            ldsm4(al1, sb + TL_OFF + 144u * (m0 + 16 + aRow) + 32u * ks + aKoff);
#pragma unroll
            for (int ntp = 0; ntp < 4; ntp++) {
                uint32_t b4[4];
                ldsm4(b4, sb + BH_OFF + bBase + 2304u * ntp + 32u * ks);
                mma16816h(acc[0][2 * ntp], ah0, b4[0], b4[1]);
                mma16816h(acc[1][2 * ntp], ah1, b4[0], b4[1]);
                mma16816h(acc[0][2 * ntp + 1], ah0, b4[2], b4[3]);
                mma16816h(acc[1][2 * ntp + 1], ah1, b4[2], b4[3]);
                mma16816h(acc[0][2 * ntp], al0, b4[0], b4[1]);
                mma16816h(acc[1][2 * ntp], al1, b4[0], b4[1]);
                mma16816h(acc[0][2 * ntp + 1], al0, b4[2], b4[3]);
                mma16816h(acc[1][2 * ntp + 1], al1, b4[2], b4[3]);
            }
        }
        __syncthreads();   // Th/Tl reads done before Ds overlay writes

        // ---- stage D to swizzled SMEM: float4 slot = e*16 + (c4^(e&15)) ----
#pragma unroll
        for (int mt = 0; mt < 2; mt++) {
            int eb = m0 + mt * 16 + (lane >> 2);
            int h2i = lane & 1;
            int c4b = (lane & 3) >> 1;
#pragma unroll
            for (int nt = 0; nt < 8; nt++) {
                int c4 = nt * 2 + c4b;
                float2 v0 = make_float2(acc[mt][nt][0], acc[mt][nt][1]);
                float2 v1 = make_float2(acc[mt][nt][2], acc[mt][nt][3]);
                int e0 = eb, e1 = eb + 8;
                ((float2*)(Ds + (e0 * 16 + (c4 ^ (e0 & 15))) * 4))[h2i] = v0;
                ((float2*)(Ds + (e1 * 16 + (c4 ^ (e1 & 15))) * 4))[h2i] = v1;
            }
        }
        __syncthreads();

        // ---- epilogue: segmented min over 8 sorted edges, atomicMin ----
        {
            const float4* Ds4 = (const float4*)Ds;
            int ty = tid >> 3, tx = tid & 7;
            int cur = -2;
            float4 mA, mB;
#pragma unroll
            for (int r = 0; r < 8; r++) {
                int e = ty * 8 + r;
                int d = dstL[e];
                float4 a = Ds4[e * 16 + (tx ^ (e & 15))];
                float4 b = Ds4[e * 16 + ((8 + tx) ^ (e & 15))];
                if (r == 0 || d != cur) {
                    if (r > 0 && cur >= 0) {
                        unsigned* p0 = aggr + (size_t)cur * H + tx * 4;
                        atomicMin(p0 + 0, fenc(mA.x));
                        atomicMin(p0 + 1, fenc(mA.y));
                        atomicMin(p0 + 2, fenc(mA.z));
                        atomicMin(p0 + 3, fenc(mA.w));
                        unsigned* p1 = p0 + 32;
                        atomicMin(p1 + 0, fenc(mB.x));
                        atomicMin(p1 + 1, fenc(mB.y));
                        atomicMin(p1 + 2, fenc(mB.z));
                        atomicMin(p1 + 3, fenc(mB.w));
                    }
                    cur = d;
                    mA = a; mB = b;
                } else {
                    mA.x = fminf(mA.x, a.x); mA.y = fminf(mA.y, a.y);
                    mA.z = fminf(mA.z, a.z); mA.w = fminf(mA.w, a.w);
                    mB.x = fminf(mB.x, b.x); mB.y = fminf(mB.y, b.y);
                    mB.z = fminf(mB.z, b.z); mB.w = fminf(mB.w, b.w);
                }
            }
            if (cur >= 0) {
                unsigned* p0 = aggr + (size_t)cur * H + tx * 4;
                atomicMin(p0 + 0, fenc(mA.x));
                atomicMin(p0 + 1, fenc(mA.y));
                atomicMin(p0 + 2, fenc(mA.z));
                atomicMin(p0 + 3, fenc(mA.w));
                unsigned* p1 = p0 + 32;
                atomicMin(p1 + 0, fenc(mB.x));
                atomicMin(p1 + 1, fenc(mB.y));
                atomicMin(p1 + 2, fenc(mB.z));
                atomicMin(p1 + 3, fenc(mB.w));
            }
        }
        __syncthreads();   // Ds/dstL dead before next tile's writes
    }
}

// ---------------- host launch ----------------------------------------------
extern "C" void kernel_launch(void* const* d_in, const int* in_sizes, int n_in,
                              void* d_out, int out_size) {
    const float* x    = (const float*)d_in[0];
    const int*   ei   = (const int*)d_in[1];
    const float* ea   = (const float*)d_in[2];
    const float* embw = (const float*)d_in[3];
    const float* embb = (const float*)d_in[4];
    const float* mw1  = (const float*)d_in[5];
    const float* mb1  = (const float*)d_in[6];
    const float* mw2  = (const float*)d_in[7];
    const float* mb2  = (const float*)d_in[8];
    const float* uw1  = (const float*)d_in[9];
    const float* ub1  = (const float*)d_in[10];
    const float* uw2  = (const float*)d_in[11];
    const float* ub2  = (const float*)d_in[12];
    const float* fcw  = (const float*)d_in[13];
    const float* fcb  = (const float*)d_in[14];
    float* out = (float*)d_out;

    int N = in_sizes[0];
    int E = in_sizes[2];
    int L = in_sizes[6] / H;
    const int* src = ei;
    const int* dstp = ei + E;

    float* hbuf; float* Abuf; unsigned* aggr;
    int* cnt; int* cursor; int* perm;
    __half* Bh;
    cudaGetSymbolAddress((void**)&hbuf, g_h);
    cudaGetSymbolAddress((void**)&Abuf, g_A);
    cudaGetSymbolAddress((void**)&aggr, g_aggr);
    cudaGetSymbolAddress((void**)&cnt, g_cnt);
    cudaGetSymbolAddress((void**)&cursor, g_cursor);
    cudaGetSymbolAddress((void**)&perm, g_perm);
    cudaGetSymbolAddress((void**)&Bh, g_Bh);

    const size_t sm64  = (64 * 64 + 64 * 128) * 4;
    const size_t sm128 = (128 * 64 + 128 * 128 + 64) * 4;
    cudaFuncSetAttribute(edge_mma_kernel,
                         cudaFuncAttributeMaxDynamicSharedMemorySize, SMEM_EDGE);
    cudaFuncSetAttribute((node_gemm<64, false, false>),
                         cudaFuncAttributeMaxDynamicSharedMemorySize, (int)sm64);
    cudaFuncSetAttribute((node_gemm<128, true, true>),
                         cudaFuncAttributeMaxDynamicSharedMemorySize, (int)sm128);

    int ntiles = (E + 127) / 128;
    int edgeGrid = 148 * 4;
    if (edgeGrid > ntiles) edgeGrid = ntiles;
    int nodeBlocks = (N + 127) / 128;

    // embedding (+ zero cnt)
    embed_kernel<<<(N * H + 255) / 256, 256>>>(x, embw, embb, hbuf, cnt, N);
    // counting sort by dst (+ B fp16 prep, + aggr poison)
    count_kernel<<<(E + 255) / 256, 256>>>(dstp, cnt, E);
    scan_prep_kernel<<<1, 1024>>>(cnt, cursor, N, mw2, L);
    scatter_kernel<<<(E + 255) / 256, 256>>>(dstp, cursor, perm, aggr, E,
                                             N * H / 4);

    for (int l = 0; l < L; l++) {
        const float* w1 = mw1 + (size_t)l * (H + 1) * H;   // [65,64]
        // A = h @ W1[:64] + b1  (per-node hoist of per-edge msg layer 1)
        node_gemm<64, false, false><<<nodeBlocks, 128, sm64>>>(
            hbuf, nullptr, w1, mb1 + (size_t)l * H, Abuf, N, nullptr, nullptr);
        // tensor-pipe edge message + scatter-min
        edge_mma_kernel<<<edgeGrid, 128, SMEM_EDGE>>>(
            Abuf, src, dstp, ea, perm, w1 + (size_t)H * H,
            Bh + (size_t)l * (64 * 72), aggr, E, ntiles);
        // update MLP layer 1 (fused aggr decode + b2 + re-poison)
        node_gemm<128, true, true><<<nodeBlocks, 128, sm128>>>(
            hbuf, aggr, uw1 + (size_t)l * 2 * H * H, ub1 + (size_t)l * H,
            Abuf, N, mb2 + (size_t)l * H, aggr);
        // update MLP layer 2
        node_gemm<64, false, false><<<nodeBlocks, 128, sm64>>>(
            Abuf, nullptr, uw2 + (size_t)l * H * H, ub2 + (size_t)l * H,
            hbuf, N, nullptr, nullptr);
    }

    fc_kernel<<<(N + 255) / 256, 256>>>(hbuf, fcw, fcb, out, N);
}